// round 6
// baseline (speedup 1.0000x reference)
#include <cuda_runtime.h>

// SNNLayer: element-wise LIF-style recurrence.
//   m_t = 0.9*m_{t-1} + gate*gamma*w_m + s_{t-1}*(0.1*w_r - 0.5)
//   s_t = sigmoid(8*(m_t - 0.5))
// T=64, B=32, N=16384. Output spike_trace [T,B,N] fp32.
//
// HBM-bound: 384 MB streamed. One thread per float4 column, serial over T,
// 2-deep software-pipelined gate/gamma prefetch (>=64KB in flight per SM vs
// ~25KB latency-BW product), streaming cache hints (each byte touched once).

#define T_STEPS 64
#define B_DIM 32
#define N_DIM 16384
#define BN4 ((B_DIM * N_DIM) / 4)   // 131072 float4 columns
#define N4  (N_DIM / 4)             // 4096 float4 per batch row

__global__ __launch_bounds__(256) void snn_kernel(
    const float4* __restrict__ gate,   // [T, B*N/4]
    const float4* __restrict__ gamma,  // [T, B*N/4]
    const float4* __restrict__ mw,     // [N/4] membrane_weight
    const float4* __restrict__ rw,     // [N/4] recurrent_weight
    float4* __restrict__ out)          // [T, B*N/4]
{
    const int idx  = blockIdx.x * blockDim.x + threadIdx.x;  // 0..BN4-1
    const int nvec = idx & (N4 - 1);                         // n/4 within a row

    const float4 w4  = __ldg(&mw[nvec]);
    const float4 rw4 = __ldg(&rw[nvec]);
    // fold recurrent drive + threshold-reset: s_prev*(0.1*rw - 0.5)
    const float c0 = fmaf(0.1f, rw4.x, -0.5f);
    const float c1 = fmaf(0.1f, rw4.y, -0.5f);
    const float c2 = fmaf(0.1f, rw4.z, -0.5f);
    const float c3 = fmaf(0.1f, rw4.w, -0.5f);

    float m0 = 0.f, m1 = 0.f, m2 = 0.f, m3 = 0.f;
    float s0 = 0.f, s1 = 0.f, s2 = 0.f, s3 = 0.f;

    // 2-deep software pipeline: loads for t+1 and t+2 in flight while
    // computing step t.
    float4 g0  = __ldcs(&gate[idx]);
    float4 ga0 = __ldcs(&gamma[idx]);
    float4 g1  = __ldcs(&gate[(long)BN4 + idx]);
    float4 ga1 = __ldcs(&gamma[(long)BN4 + idx]);

    #pragma unroll 4
    for (int t = 0; t < T_STEPS; t++) {
        float4 g2, ga2;
        if (t + 2 < T_STEPS) {
            const long off = (long)(t + 2) * BN4 + idx;
            g2  = __ldcs(&gate[off]);
            ga2 = __ldcs(&gamma[off]);
        }

        // m = 0.9*m + (g*ga)*w + s*c
        m0 = fmaf(0.9f, m0, fmaf(g0.x * ga0.x, w4.x, s0 * c0));
        m1 = fmaf(0.9f, m1, fmaf(g0.y * ga0.y, w4.y, s1 * c1));
        m2 = fmaf(0.9f, m2, fmaf(g0.z * ga0.z, w4.z, s2 * c2));
        m3 = fmaf(0.9f, m3, fmaf(g0.w * ga0.w, w4.w, s3 * c3));

        // s = sigmoid(8*(m-0.5)) = 1/(1+exp(-8m+4))
        s0 = __frcp_rn(1.0f + __expf(fmaf(-8.0f, m0, 4.0f)));
        s1 = __frcp_rn(1.0f + __expf(fmaf(-8.0f, m1, 4.0f)));
        s2 = __frcp_rn(1.0f + __expf(fmaf(-8.0f, m2, 4.0f)));
        s3 = __frcp_rn(1.0f + __expf(fmaf(-8.0f, m3, 4.0f)));

        float4 s_out = make_float4(s0, s1, s2, s3);
        __stcs(&out[(long)t * BN4 + idx], s_out);

        g0 = g1;  ga0 = ga1;
        g1 = g2;  ga1 = ga2;
    }
}

extern "C" void kernel_launch(void* const* d_in, const int* in_sizes, int n_in,
                              void* d_out, int out_size)
{
    // metadata order: membrane0 [B,N], spikes0 [B,N], sinusoidal_gate [T,B,N],
    //                 gamma [T,B,N], membrane_weight [N], recurrent_weight [N]
    const float4* gate  = (const float4*)d_in[2];
    const float4* gamma = (const float4*)d_in[3];
    const float4* mw    = (const float4*)d_in[4];
    const float4* rw    = (const float4*)d_in[5];
    float4* out = (float4*)d_out;

    const int threads = 256;
    const int blocks  = BN4 / threads;  // 512
    snn_kernel<<<blocks, threads>>>(gate, gamma, mw, rw, out);
}

// round 7
// speedup vs baseline: 1.0275x; 1.0275x over previous
#include <cuda_runtime.h>

// SNNLayer: element-wise LIF-style recurrence.
//   m_t = 0.9*m_{t-1} + gate*gamma*w_m + s_{t-1}*(0.1*w_r - 0.5)
//   s_t = sigmoid(8*(m_t - 0.5))
// T=64, B=32, N=16384. Output spike_trace [T,B,N] fp32.
//
// HBM-bound (384 MiB streamed). R6 finding: dram stuck at 73.7% due to
// CTA residency imbalance (512 CTAs / 148 SMs = 3.46/SM, 4-vs-3 split ->
// 25% tail). Fix: 128-thread CTAs, 1024 blocks -> ~7/SM, 14% worst-case
// imbalance. Sigmoid folded to single ex2.approx + rcp.approx per element.

#define T_STEPS 64
#define B_DIM 32
#define N_DIM 16384
#define BN4 ((B_DIM * N_DIM) / 4)   // 131072 float4 columns
#define N4  (N_DIM / 4)             // 4096 float4 per batch row

// -8*log2(e), 4*log2(e)
#define NEG8_LOG2E (-11.541560327111708f)
#define POS4_LOG2E (5.770780163555854f)

__device__ __forceinline__ float fast_ex2(float x) {
    float r;
    asm("ex2.approx.ftz.f32 %0, %1;" : "=f"(r) : "f"(x));
    return r;
}
__device__ __forceinline__ float fast_rcp(float x) {
    float r;
    asm("rcp.approx.ftz.f32 %0, %1;" : "=f"(r) : "f"(x));
    return r;
}
// sigmoid(8*(m-0.5)) = 1/(1+exp2(-8*log2e*m + 4*log2e))
__device__ __forceinline__ float fast_sig(float m) {
    return fast_rcp(1.0f + fast_ex2(fmaf(NEG8_LOG2E, m, POS4_LOG2E)));
}

__global__ __launch_bounds__(128) void snn_kernel(
    const float4* __restrict__ gate,   // [T, B*N/4]
    const float4* __restrict__ gamma,  // [T, B*N/4]
    const float4* __restrict__ mw,     // [N/4] membrane_weight
    const float4* __restrict__ rw,     // [N/4] recurrent_weight
    float4* __restrict__ out)          // [T, B*N/4]
{
    const int idx  = blockIdx.x * blockDim.x + threadIdx.x;  // 0..BN4-1
    const int nvec = idx & (N4 - 1);                         // n/4 within a row

    const float4 w4  = __ldg(&mw[nvec]);
    const float4 rw4 = __ldg(&rw[nvec]);
    // fold recurrent drive + threshold-reset: s_prev*(0.1*rw - 0.5)
    const float c0 = fmaf(0.1f, rw4.x, -0.5f);
    const float c1 = fmaf(0.1f, rw4.y, -0.5f);
    const float c2 = fmaf(0.1f, rw4.z, -0.5f);
    const float c3 = fmaf(0.1f, rw4.w, -0.5f);

    float m0 = 0.f, m1 = 0.f, m2 = 0.f, m3 = 0.f;
    float s0 = 0.f, s1 = 0.f, s2 = 0.f, s3 = 0.f;

    // 2-deep software pipeline: loads for t+1 and t+2 in flight while
    // computing step t.
    float4 g0  = __ldcs(&gate[idx]);
    float4 ga0 = __ldcs(&gamma[idx]);
    float4 g1  = __ldcs(&gate[(long)BN4 + idx]);
    float4 ga1 = __ldcs(&gamma[(long)BN4 + idx]);

    #pragma unroll 4
    for (int t = 0; t < T_STEPS; t++) {
        float4 g2, ga2;
        if (t + 2 < T_STEPS) {
            const long off = (long)(t + 2) * BN4 + idx;
            g2  = __ldcs(&gate[off]);
            ga2 = __ldcs(&gamma[off]);
        }

        // m = 0.9*m + (g*ga)*w + s*c
        m0 = fmaf(0.9f, m0, fmaf(g0.x * ga0.x, w4.x, s0 * c0));
        m1 = fmaf(0.9f, m1, fmaf(g0.y * ga0.y, w4.y, s1 * c1));
        m2 = fmaf(0.9f, m2, fmaf(g0.z * ga0.z, w4.z, s2 * c2));
        m3 = fmaf(0.9f, m3, fmaf(g0.w * ga0.w, w4.w, s3 * c3));

        s0 = fast_sig(m0);
        s1 = fast_sig(m1);
        s2 = fast_sig(m2);
        s3 = fast_sig(m3);

        float4 s_out = make_float4(s0, s1, s2, s3);
        __stcs(&out[(long)t * BN4 + idx], s_out);

        g0 = g1;  ga0 = ga1;
        g1 = g2;  ga1 = ga2;
    }
}

extern "C" void kernel_launch(void* const* d_in, const int* in_sizes, int n_in,
                              void* d_out, int out_size)
{
    // metadata order: membrane0 [B,N], spikes0 [B,N], sinusoidal_gate [T,B,N],
    //                 gamma [T,B,N], membrane_weight [N], recurrent_weight [N]
    const float4* gate  = (const float4*)d_in[2];
    const float4* gamma = (const float4*)d_in[3];
    const float4* mw    = (const float4*)d_in[4];
    const float4* rw    = (const float4*)d_in[5];
    float4* out = (float4*)d_out;

    const int threads = 128;
    const int blocks  = BN4 / threads;  // 1024
    snn_kernel<<<blocks, threads>>>(gate, gamma, mw, rw, out);
}

// round 16
// speedup vs baseline: 1.0421x; 1.0142x over previous
#include <cuda_runtime.h>

// SNNLayer: element-wise LIF-style recurrence.
//   m_t = 0.9*m_{t-1} + gate*gamma*w_m + s_{t-1}*(0.1*w_r - 0.5)
//   s_t = sigmoid(8*(m_t - 0.5))
// T=64, B=32, N=16384. Output spike_trace [T,B,N] fp32.
//
// R7 post-mortem: occ was grid-limited at 40.5% (4096 warps total); DRAM
// stuck at 74% from demand gaps, not residency imbalance. Fix: float2 per
// thread -> 8192 warps -> ~75% occ, 2x independent load chains. Pipeline
// depth 2, streaming hints, single ex2+rcp sigmoid.

#define T_STEPS 64
#define B_DIM 32
#define N_DIM 16384
#define BN2 ((B_DIM * N_DIM) / 2)   // 262144 float2 columns
#define N2  (N_DIM / 2)             // 8192 float2 per batch row

// -8*log2(e), 4*log2(e)
#define NEG8_LOG2E (-11.541560327111708f)
#define POS4_LOG2E (5.770780163555854f)

__device__ __forceinline__ float fast_ex2(float x) {
    float r;
    asm("ex2.approx.ftz.f32 %0, %1;" : "=f"(r) : "f"(x));
    return r;
}
__device__ __forceinline__ float fast_rcp(float x) {
    float r;
    asm("rcp.approx.ftz.f32 %0, %1;" : "=f"(r) : "f"(x));
    return r;
}
// sigmoid(8*(m-0.5)) = 1/(1+exp2(-8*log2e*m + 4*log2e))
__device__ __forceinline__ float fast_sig(float m) {
    return fast_rcp(1.0f + fast_ex2(fmaf(NEG8_LOG2E, m, POS4_LOG2E)));
}

__global__ __launch_bounds__(128) void snn_kernel(
    const float2* __restrict__ gate,   // [T, B*N/2]
    const float2* __restrict__ gamma,  // [T, B*N/2]
    const float2* __restrict__ mw,     // [N/2] membrane_weight
    const float2* __restrict__ rw,     // [N/2] recurrent_weight
    float2* __restrict__ out)          // [T, B*N/2]
{
    const int idx  = blockIdx.x * blockDim.x + threadIdx.x;  // 0..BN2-1
    const int nvec = idx & (N2 - 1);                         // n/2 within a row

    const float2 w2  = __ldg(&mw[nvec]);
    const float2 rw2 = __ldg(&rw[nvec]);
    // fold recurrent drive + threshold-reset: s_prev*(0.1*rw - 0.5)
    const float c0 = fmaf(0.1f, rw2.x, -0.5f);
    const float c1 = fmaf(0.1f, rw2.y, -0.5f);

    float m0 = 0.f, m1 = 0.f;
    float s0 = 0.f, s1 = 0.f;

    // 2-deep software pipeline: loads for t+1 and t+2 in flight while
    // computing step t.
    float2 g0  = __ldcs(&gate[idx]);
    float2 ga0 = __ldcs(&gamma[idx]);
    float2 g1  = __ldcs(&gate[(long)BN2 + idx]);
    float2 ga1 = __ldcs(&gamma[(long)BN2 + idx]);

    #pragma unroll 4
    for (int t = 0; t < T_STEPS; t++) {
        float2 g2, ga2;
        if (t + 2 < T_STEPS) {
            const long off = (long)(t + 2) * BN2 + idx;
            g2  = __ldcs(&gate[off]);
            ga2 = __ldcs(&gamma[off]);
        }

        // m = 0.9*m + (g*ga)*w + s*c
        m0 = fmaf(0.9f, m0, fmaf(g0.x * ga0.x, w2.x, s0 * c0));
        m1 = fmaf(0.9f, m1, fmaf(g0.y * ga0.y, w2.y, s1 * c1));

        s0 = fast_sig(m0);
        s1 = fast_sig(m1);

        __stcs(&out[(long)t * BN2 + idx], make_float2(s0, s1));

        g0 = g1;  ga0 = ga1;
        g1 = g2;  ga1 = ga2;
    }
}

extern "C" void kernel_launch(void* const* d_in, const int* in_sizes, int n_in,
                              void* d_out, int out_size)
{
    // metadata order: membrane0 [B,N], spikes0 [B,N], sinusoidal_gate [T,B,N],
    //                 gamma [T,B,N], membrane_weight [N], recurrent_weight [N]
    const float2* gate  = (const float2*)d_in[2];
    const float2* gamma = (const float2*)d_in[3];
    const float2* mw    = (const float2*)d_in[4];
    const float2* rw    = (const float2*)d_in[5];
    float2* out = (float2*)d_out;

    const int threads = 128;
    const int blocks  = BN2 / threads;  // 2048
    snn_kernel<<<blocks, threads>>>(gate, gamma, mw, rw, out);
}